// round 2
// baseline (speedup 1.0000x reference)
#include <cuda_runtime.h>

#define NS 16384
#define NQ 16384
#define DIM 64
#define NC 64

// Scratch (no allocs allowed): precomputed squared norms + labels
__device__ float g_sq_s[NS];
__device__ float g_sq_q[NQ];
__device__ int   g_lab[NS];

// Prep: ||s||^2, ||q||^2, label = first argmax of one-hot row
__global__ __launch_bounds__(256) void prep_kernel(const float* __restrict__ S,
                                                   const float* __restrict__ Q,
                                                   const float* __restrict__ OH) {
    int row = blockIdx.x * blockDim.x + threadIdx.x;
    if (row >= NS) return;
    {
        const float4* s4 = (const float4*)(S + (size_t)row * DIM);
        float acc = 0.f;
        #pragma unroll
        for (int i = 0; i < DIM / 4; i++) {
            float4 v = s4[i];
            acc += v.x * v.x + v.y * v.y + v.z * v.z + v.w * v.w;
        }
        g_sq_s[row] = acc;
    }
    {
        const float4* q4 = (const float4*)(Q + (size_t)row * DIM);
        float acc = 0.f;
        #pragma unroll
        for (int i = 0; i < DIM / 4; i++) {
            float4 v = q4[i];
            acc += v.x * v.x + v.y * v.y + v.z * v.z + v.w * v.w;
        }
        g_sq_q[row] = acc;
    }
    {
        const float* oh = OH + (size_t)row * NC;
        float best = oh[0];
        int bi = 0;
        #pragma unroll 8
        for (int c = 1; c < NC; c++) {
            float v = oh[c];
            if (v > best) { best = v; bi = c; }  // strict > keeps first argmax
        }
        g_lab[row] = bi;
    }
}

// Main: each block owns 64 queries, streams all 16384 supports in 64-chunks.
// Thread (tx,ty): queries ty*4..ty*4+3, supports tx*4..tx*4+3 within chunk.
__global__ __launch_bounds__(256) void knn_kernel(const float* __restrict__ S,
                                                  const float* __restrict__ Q,
                                                  float* __restrict__ out) {
    __shared__ float Qs[DIM][64];   // [k][q] transposed
    __shared__ float Ss[DIM][64];   // [k][s] transposed
    __shared__ float sqs_sh[64];
    __shared__ int   idx_sh[64];
    __shared__ int   lab_sh[64];

    const int tid = threadIdx.x;
    const int tx = tid & 15;        // support slice
    const int ty = tid >> 4;        // query slice
    const int qbase = blockIdx.x * 64;

    // Load Q tile transposed: 64 rows x 16 float4 = 1024 float4, 4 per thread
    #pragma unroll
    for (int it = 0; it < 4; it++) {
        int i = tid + it * 256;
        int r = i >> 4;
        int k4 = (i & 15) * 4;
        float4 v = *(const float4*)(Q + (size_t)(qbase + r) * DIM + k4);
        Qs[k4 + 0][r] = v.x;
        Qs[k4 + 1][r] = v.y;
        Qs[k4 + 2][r] = v.z;
        Qs[k4 + 3][r] = v.w;
    }
    __syncthreads();

    float sqq[4];
    #pragma unroll
    for (int i = 0; i < 4; i++) sqq[i] = g_sq_q[qbase + ty * 4 + i];

    float best_d2[4];
    int   best_idx[4];
    #pragma unroll
    for (int i = 0; i < 4; i++) { best_d2[i] = 3.4e38f; best_idx[i] = 0; }

    for (int chunk = 0; chunk < NS / 64; chunk++) {
        // Load S chunk transposed (same pattern as Q)
        #pragma unroll
        for (int it = 0; it < 4; it++) {
            int i = tid + it * 256;
            int r = i >> 4;
            int k4 = (i & 15) * 4;
            float4 v = *(const float4*)(S + (size_t)(chunk * 64 + r) * DIM + k4);
            Ss[k4 + 0][r] = v.x;
            Ss[k4 + 1][r] = v.y;
            Ss[k4 + 2][r] = v.z;
            Ss[k4 + 3][r] = v.w;
        }
        if (tid < 64) sqs_sh[tid] = g_sq_s[chunk * 64 + tid];
        __syncthreads();

        float acc[4][4];
        #pragma unroll
        for (int i = 0; i < 4; i++)
            #pragma unroll
            for (int j = 0; j < 4; j++) acc[i][j] = 0.f;

        #pragma unroll
        for (int k = 0; k < DIM; k++) {
            float4 qv = *(const float4*)&Qs[k][ty * 4];
            float4 sv = *(const float4*)&Ss[k][tx * 4];
            float qr[4] = {qv.x, qv.y, qv.z, qv.w};
            float sr[4] = {sv.x, sv.y, sv.z, sv.w};
            #pragma unroll
            for (int i = 0; i < 4; i++)
                #pragma unroll
                for (int j = 0; j < 4; j++)
                    acc[i][j] = fmaf(qr[i], sr[j], acc[i][j]);
        }

        // Epilogue: d2 = sqq + sqs - 2*cross; strict < keeps first-min
        #pragma unroll
        for (int j = 0; j < 4; j++) {
            int sidx = chunk * 64 + tx * 4 + j;
            float sqsj = sqs_sh[tx * 4 + j];
            #pragma unroll
            for (int i = 0; i < 4; i++) {
                float d2 = fmaf(-2.f, acc[i][j], sqq[i] + sqsj);
                if (d2 < best_d2[i]) { best_d2[i] = d2; best_idx[i] = sidx; }
            }
        }
        __syncthreads();
    }

    // Reduce across the 16 tx-threads per query (min d2, tie -> min idx)
    #pragma unroll
    for (int i = 0; i < 4; i++) {
        float d = best_d2[i];
        int   x = best_idx[i];
        #pragma unroll
        for (int off = 8; off > 0; off >>= 1) {
            float od = __shfl_down_sync(0xffffffffu, d, off, 16);
            int   ox = __shfl_down_sync(0xffffffffu, x, off, 16);
            if (od < d || (od == d && ox < x)) { d = od; x = ox; }
        }
        if (tx == 0) idx_sh[ty * 4 + i] = x;
    }
    __syncthreads();

    if (tid < 64) lab_sh[tid] = g_lab[idx_sh[tid]];
    __syncthreads();

    // Cooperative one-hot write: 64 rows x 64 cols, 16 floats per thread
    {
        int row = tid >> 2;
        int cseg = (tid & 3) * 16;
        int lab = lab_sh[row];
        float* orow = out + (size_t)(qbase + row) * NC + cseg;
        #pragma unroll
        for (int c4 = 0; c4 < 16; c4 += 4) {
            float4 v;
            v.x = (cseg + c4 + 0 == lab) ? 1.f : 0.f;
            v.y = (cseg + c4 + 1 == lab) ? 1.f : 0.f;
            v.z = (cseg + c4 + 2 == lab) ? 1.f : 0.f;
            v.w = (cseg + c4 + 3 == lab) ? 1.f : 0.f;
            *(float4*)(orow + c4) = v;
        }
    }
}

extern "C" void kernel_launch(void* const* d_in, const int* in_sizes, int n_in,
                              void* d_out, int out_size) {
    const float* S  = (const float*)d_in[0];  // support_embeddings [NS, D]
    const float* Q  = (const float*)d_in[1];  // query_embeddings   [NQ, D]
    const float* OH = (const float*)d_in[2];  // support_labels_onehot [NS, NC]
    float* out = (float*)d_out;               // [NQ, NC] fp32

    prep_kernel<<<NS / 256, 256>>>(S, Q, OH);
    knn_kernel<<<NQ / 64, 256>>>(S, Q, out);
}

// round 3
// speedup vs baseline: 1.5825x; 1.5825x over previous
#include <cuda_runtime.h>
#include <cstdint>

#define NS 16384
#define NQ 16384
#define DIM 64
#define NC 64

#define QT 128              // queries per block
#define ST 128              // supports per chunk
#define NCHUNK (NS / ST)    // 128

__device__ float g_sq_s[NS];
__device__ int   g_lab[NS];

__device__ __forceinline__ unsigned long long fma2(unsigned long long a,
                                                   unsigned long long b,
                                                   unsigned long long c) {
    unsigned long long d;
    asm("fma.rn.f32x2 %0, %1, %2, %3;" : "=l"(d) : "l"(a), "l"(b), "l"(c));
    return d;
}

// Prep: ||s||^2 and label = first argmax of one-hot row
__global__ __launch_bounds__(256) void prep_kernel(const float* __restrict__ S,
                                                   const float* __restrict__ OH) {
    int row = blockIdx.x * blockDim.x + threadIdx.x;
    if (row >= NS) return;
    {
        const float4* s4 = (const float4*)(S + (size_t)row * DIM);
        float acc = 0.f;
        #pragma unroll
        for (int i = 0; i < DIM / 4; i++) {
            float4 v = s4[i];
            acc += v.x * v.x + v.y * v.y + v.z * v.z + v.w * v.w;
        }
        g_sq_s[row] = acc;
    }
    {
        const float* oh = OH + (size_t)row * NC;
        float best = oh[0];
        int bi = 0;
        #pragma unroll 8
        for (int c = 1; c < NC; c++) {
            float v = oh[c];
            if (v > best) { best = v; bi = c; }
        }
        g_lab[row] = bi;
    }
}

// Dynamic smem layout (floats):
//   Qdup   [64][256]      offset 0       (Q transposed, each value duplicated)
//   Ss     [2][64][128]   offset 16384   (S transposed, f4-swizzled, double buf)
//   sqs_sh [2][128]       offset 32768
//   idx_sh [128] (int)    offset 33024
#define SMEM_FLOATS (64 * 256 + 2 * 64 * 128 + 2 * 128 + 128)

__global__ __launch_bounds__(256) void knn_kernel(const float* __restrict__ S,
                                                  const float* __restrict__ Q,
                                                  float* __restrict__ out) {
    extern __shared__ float smem[];
    float* Qdup   = smem;
    float* Ssm    = smem + 64 * 256;
    float* sqs_sh = smem + 64 * 256 + 2 * 64 * 128;
    int*   idx_sh = (int*)(sqs_sh + 2 * 128);

    const int tid = threadIdx.x;
    const int sx  = tid & 15;     // 16 support groups of 8
    const int qy  = tid >> 4;     // 16 query groups of 8
    const int qbase = blockIdx.x * QT;

    // ---- Q tile: transpose + duplicate (one time) ----
    {
        const float4* Qg = (const float4*)(Q + (size_t)qbase * DIM);
        #pragma unroll
        for (int i = 0; i < 8; i++) {
            int g = tid + i * 256;
            float4 v = Qg[g];
            int q  = g >> 4;
            int k4 = (g & 15) * 4;
            float* dst = Qdup + k4 * 256 + 2 * q;
            dst[0]   = v.x; dst[1]   = v.x;
            dst[256] = v.y; dst[257] = v.y;
            dst[512] = v.z; dst[513] = v.z;
            dst[768] = v.w; dst[769] = v.w;
        }
    }

    // ---- S chunk staging helpers ----
    float4 pf[8];
    unsigned long long sqpre = 0ull;

    // load chunk c (coalesced) into registers
    auto ldchunk = [&](int c) {
        const float4* Sg = (const float4*)(S + (size_t)c * ST * DIM);
        #pragma unroll
        for (int i = 0; i < 8; i++) pf[i] = Sg[tid + i * 256];
        if (tid < 64)
            sqpre = ((const unsigned long long*)(g_sq_s + c * ST))[tid];
    };
    // store registers into buffer buf, transposed [k][s] with f4 XOR swizzle
    auto stchunk = [&](int buf) {
        float* dst = Ssm + buf * (64 * 128);
        #pragma unroll
        for (int i = 0; i < 8; i++) {
            int g  = tid + i * 256;
            int s  = g >> 4;
            int k4 = (g & 15) * 4;
            int f  = (k4 >> 2) & 7;                      // same for all 4 comps
            int phys = ((s >> 2) ^ f) * 4 + (s & 3);
            float v[4] = {pf[i].x, pf[i].y, pf[i].z, pf[i].w};
            #pragma unroll
            for (int cc = 0; cc < 4; cc++)
                dst[(k4 + cc) * 128 + phys] = v[cc];
        }
        if (tid < 64)
            ((unsigned long long*)(sqs_sh + buf * 128))[tid] = sqpre;
    };

    ldchunk(0);
    stchunk(0);
    __syncthreads();

    float best[8];
    int   bidx[8];
    #pragma unroll
    for (int i = 0; i < 8; i++) { best[i] = 3.4e38f; bidx[i] = 0; }

    const unsigned long long NEG2 = 0xC0000000C0000000ull;  // (-2.f, -2.f)
    const float* Qb = Qdup + qy * 16;

    for (int c = 0; c < NCHUNK; c++) {
        ldchunk((c + 1) & (NCHUNK - 1));   // prefetch next (wraps; redundant on last)

        unsigned long long acc[8][4];
        #pragma unroll
        for (int i = 0; i < 8; i++)
            #pragma unroll
            for (int p = 0; p < 4; p++) acc[i][p] = 0ull;

        const float* Sb = Ssm + (c & 1) * (64 * 128);

        for (int k0 = 0; k0 < 64; k0 += 8) {
            #pragma unroll
            for (int kk = 0; kk < 8; kk++) {
                int k = k0 + kk;
                int f = (k >> 2) & 7;
                const float* qp = Qb + k * 256;
                ulonglong2 qa = *(const ulonglong2*)(qp);
                ulonglong2 qb = *(const ulonglong2*)(qp + 4);
                ulonglong2 qc = *(const ulonglong2*)(qp + 8);
                ulonglong2 qd = *(const ulonglong2*)(qp + 12);
                unsigned long long qv[8] = {qa.x, qa.y, qb.x, qb.y,
                                            qc.x, qc.y, qd.x, qd.y};
                const float* spb = Sb + k * 128 + ((sx ^ f) * 4);
                ulonglong2 sa = *(const ulonglong2*)(spb);
                ulonglong2 sb = *(const ulonglong2*)(spb + 64);
                unsigned long long sv[4] = {sa.x, sa.y, sb.x, sb.y};
                #pragma unroll
                for (int i = 0; i < 8; i++)
                    #pragma unroll
                    for (int p = 0; p < 4; p++)
                        acc[i][p] = fma2(qv[i], sv[p], acc[i][p]);
            }
        }

        // epilogue: d2' = ||s||^2 - 2*cross (|q|^2 constant per query -> same argmin)
        const float* sq_c = sqs_sh + (c & 1) * 128;
        unsigned long long sqp[4] = {
            *(const unsigned long long*)(sq_c + sx * 4),
            *(const unsigned long long*)(sq_c + sx * 4 + 2),
            *(const unsigned long long*)(sq_c + 64 + sx * 4),
            *(const unsigned long long*)(sq_c + 64 + sx * 4 + 2)};
        int sbase[4] = {c * ST + sx * 4, c * ST + sx * 4 + 2,
                        c * ST + 64 + sx * 4, c * ST + 64 + sx * 4 + 2};
        #pragma unroll
        for (int i = 0; i < 8; i++) {
            #pragma unroll
            for (int p = 0; p < 4; p++) {
                unsigned long long d2 = fma2(NEG2, acc[i][p], sqp[p]);
                float lo = __uint_as_float((unsigned)(d2 & 0xffffffffull));
                float hi = __uint_as_float((unsigned)(d2 >> 32));
                if (lo < best[i]) { best[i] = lo; bidx[i] = sbase[p]; }
                if (hi < best[i]) { best[i] = hi; bidx[i] = sbase[p] + 1; }
            }
        }

        stchunk((c + 1) & 1);
        __syncthreads();
    }

    // ---- reduce across the 16 sx-threads per query (min d2, tie -> min idx) ----
    #pragma unroll
    for (int i = 0; i < 8; i++) {
        float d = best[i];
        int   x = bidx[i];
        #pragma unroll
        for (int off = 8; off > 0; off >>= 1) {
            float od = __shfl_down_sync(0xffffffffu, d, off, 16);
            int   ox = __shfl_down_sync(0xffffffffu, x, off, 16);
            if (od < d || (od == d && ox < x)) { d = od; x = ox; }
        }
        if (sx == 0) idx_sh[qy * 8 + i] = x;
    }
    __syncthreads();

    // ---- one-hot output: 128 rows x 64 cols, 2 threads per row ----
    {
        int row  = tid >> 1;
        int half = tid & 1;
        int lab  = g_lab[idx_sh[row]];
        float* orow = out + (size_t)(qbase + row) * NC + half * 32;
        int cbase = half * 32;
        #pragma unroll
        for (int c4 = 0; c4 < 32; c4 += 4) {
            float4 v;
            v.x = (cbase + c4 + 0 == lab) ? 1.f : 0.f;
            v.y = (cbase + c4 + 1 == lab) ? 1.f : 0.f;
            v.z = (cbase + c4 + 2 == lab) ? 1.f : 0.f;
            v.w = (cbase + c4 + 3 == lab) ? 1.f : 0.f;
            *(float4*)(orow + c4) = v;
        }
    }
}

extern "C" void kernel_launch(void* const* d_in, const int* in_sizes, int n_in,
                              void* d_out, int out_size) {
    const float* S  = (const float*)d_in[0];  // support_embeddings [NS, D]
    const float* Q  = (const float*)d_in[1];  // query_embeddings   [NQ, D]
    const float* OH = (const float*)d_in[2];  // support_labels_onehot [NS, NC]
    float* out = (float*)d_out;               // [NQ, NC] fp32

    static bool attr_set = false;
    size_t smem_bytes = SMEM_FLOATS * sizeof(float);
    if (!attr_set) {
        cudaFuncSetAttribute(knn_kernel,
                             cudaFuncAttributeMaxDynamicSharedMemorySize,
                             (int)smem_bytes);
        attr_set = true;
    }

    prep_kernel<<<NS / 256, 256>>>(S, OH);
    knn_kernel<<<NQ / QT, 256, smem_bytes>>>(S, Q, out);
}